// round 15
// baseline (speedup 1.0000x reference)
#include <cuda_runtime.h>
#include <math.h>

#define D 8
#define HID 64
#define PTS_PER_CTA 8
#define THREADS 512
#define GRID 1024
#define EPSF 1e-4f
#define TWOEPSF 2e-4f

typedef unsigned long long u64;

__device__ __forceinline__ u64 pack2(float lo, float hi) {
    u64 r; asm("mov.b64 %0, {%1, %2};" : "=l"(r) : "f"(lo), "f"(hi)); return r;
}

// XLA EmitFastTanh (with_fma=true): verified bit-match with reference in R3.
__device__ __forceinline__ float xla_tanh(float x) {
    const float kClamp = 7.90531110763549805f;
    float xc = fminf(fmaxf(x, -kClamp), kClamp);
    float x2 = __fmul_rn(xc, xc);
    float num = -2.76076847742355e-16f;
    num = __fmaf_rn(x2, num,  2.00018790482477e-13f);
    num = __fmaf_rn(x2, num, -8.60467152213735e-11f);
    num = __fmaf_rn(x2, num,  5.12229709037114e-08f);
    num = __fmaf_rn(x2, num,  1.48572235717979e-05f);
    num = __fmaf_rn(x2, num,  6.37261928875436e-04f);
    num = __fmaf_rn(x2, num,  4.89352455891786e-03f);
    num = __fmul_rn(xc, num);
    float den = 1.19825839466702e-06f;
    den = __fmaf_rn(x2, den,  1.18534705686654e-04f);
    den = __fmaf_rn(x2, den,  2.26843463243900e-03f);
    den = __fmaf_rn(x2, den,  4.89352518554385e-03f);
    float r = __fdiv_rn(num, den);
    return (fabsf(x) < 0.0004f) ? x : r;
}

// smem float offsets
#define OFF_W2  0                        // 32768
#define OFF_W1  (OFF_W2 + 32768)         // 512
#define OFF_B1  (OFF_W1 + 512)           // 64
#define OFF_B2  (OFF_B1 + 64)            // 512
#define OFF_G   (OFF_B2 + 512)           // 512
#define OFF_UV  (OFF_G + 512)            // 128
#define OFF_T2  (OFF_UV + 128)           // t2d: 8p * 64h * 18 u64 = 18432 floats
#define OFF_RED (OFF_T2 + 18432)         // 16
#define SMEM_FLOATS (OFF_RED + 16)
#define SMEM_BYTES (SMEM_FLOATS * 4)

__global__ void __launch_bounds__(THREADS, 1)
rg_kernel(const float* __restrict__ pos, const float* __restrict__ uu_g,
          const float* __restrict__ vv_g, const float* __restrict__ chol,
          const float* __restrict__ W1,  const float* __restrict__ b1,
          const float* __restrict__ W2,  const float* __restrict__ b2,
          float* __restrict__ out)
{
    extern __shared__ float sm[];
    float* W2s = sm + OFF_W2;
    float* W1s = sm + OFF_W1;
    float* b1s = sm + OFF_B1;
    float* b2s = sm + OFF_B2;
    float* gS  = sm + OFF_G;
    float* uvS = sm + OFF_UV;
    u64*   t2d = (u64*)(sm + OFF_T2);   // [p][h] rows of 18 u64; entry m = (t,t)
    float* redS= sm + OFF_RED;

    const int tid  = threadIdx.x;
    const int lane = tid & 31;
    const int warp = tid >> 5;
    const int n0   = blockIdx.x * PTS_PER_CTA;

    // ---- W2 staging via cp.async: issued NOW, waited only after phase 1 ----
    {
        unsigned int w2dst =
            (unsigned int)__cvta_generic_to_shared(W2s) + (unsigned)tid * 16u;
        const char* w2src = (const char*)W2 + (size_t)tid * 16u;
        #pragma unroll
        for (int it = 0; it < 16; ++it)
            asm volatile("cp.async.cg.shared.global [%0], [%1], 16;"
                         :: "r"(w2dst + it * THREADS * 16),
                            "l"(w2src + (size_t)it * THREADS * 16) : "memory");
        asm volatile("cp.async.commit_group;" ::: "memory");
    }
    // ---- small stagings (normal loads; needed by phase 1) ----
    {
        if (tid < 128) {
            ((float4*)W1s)[tid] = ((const float4*)W1)[tid];
            ((float4*)b2s)[tid] = ((const float4*)b2)[tid];
        }
        if (tid < 64) b1s[tid] = b1[tid];
        if (tid < PTS_PER_CTA * 16) {
            int pp = tid >> 4, q = tid & 15;
            uvS[tid] = (q < 8) ? uu_g[(n0 + pp) * 8 + q]
                               : vv_g[(n0 + pp) * 8 + (q - 8)];
        }
    }
    // metric g (unamplified; any fp32 order ok) — overlaps the W2 fetch
    if (tid < 512) {
        int pp = tid >> 6, ij = tid & 63, i = ij >> 3, j = ij & 7;
        int mm = (i < j) ? i : j;
        float acc = (i == j) ? 1e-6f : 0.0f;
        for (int m = 0; m <= mm; ++m)
            acc = fmaf(chol[pp * 64 + i * 8 + m], chol[pp * 64 + j * 8 + m], acc);
        gS[tid] = acc;
    }
    __syncthreads();   // W1/b1/uv visible (W2 still in flight)

    // ---- Phase 1: 2 warps per point; t = fast_tanh((pos +- eps e_k)@W1 + b1) ----
    {
        const int p1 = warp >> 1;         // 16 warps, 8 points
        const int n  = n0 + p1;
        float posr[D];
        #pragma unroll
        for (int j = 0; j < D; ++j) posr[j] = pos[n * 8 + j];
        const int h0 = lane, h1 = lane + 32;
        const float bb0 = b1s[h0], bb1 = b1s[h1];
        #pragma unroll
        for (int mm = 0; mm < 8; ++mm) {
            int m = (warp & 1) * 8 + mm;  // m = k*2 + s; s=0 -> +eps, s=1 -> -eps
            int k = m >> 1;
            float sgn = (m & 1) ? -EPSF : EPSF;
            float acc0 = 0.0f, acc1 = 0.0f;
            #pragma unroll
            for (int j = 0; j < D; ++j) {
                float pj = posr[j];
                if (j == k) pj = __fadd_rn(pj, sgn);     // pos + offs, one rounding
                acc0 = fmaf(pj, W1s[j * 64 + h0], acc0); // ascending-j fma chain
                acc1 = fmaf(pj, W1s[j * 64 + h1], acc1);
            }
            float t0 = xla_tanh(__fadd_rn(acc0, bb0));
            float t1 = xla_tanh(__fadd_rn(acc1, bb1));
            t2d[(p1 * 64 + h0) * 18 + m] = pack2(t0, t0);   // duplicated (t,t)
            t2d[(p1 * 64 + h1) * 18 + m] = pack2(t1, t1);
        }
    }
    // W2 fetch has been overlapped by metric + phase 1; now drain it
    asm volatile("cp.async.wait_group 0;" ::: "memory");
    __syncthreads();   // W2s and t2d visible to all

    // ---- ownership: thread owns ONE point, 8 consecutive outputs ----
    const int p    = tid >> 6;               // 8 points x 64 threads
    const int slot = tid & 63;               // i = slot>>3, j = slot&7
    const int obase = slot * 8;
    const int jj   = slot & 7;
    const int ii   = slot >> 3;
    const float HRECIP = 0.5f / TWOEPSF;     // 0.5 * rn(1/2e-4); unamplified use
    const u64 NEG1 = pack2(-1.0f, -1.0f);
    const u64* td  = t2d + p * 1152;         // 64 * 18

    float partial = 0.0f;

    #pragma unroll 1
    for (int g = 0; g < 2; ++g) {            // k-groups {0..3}, {4..7}
        // ---- Phase 2: lanes = 2 adjacent outputs (same sign); native operands ----
        // accp[kk][rr] = (c+_{2rr}, c+_{2rr+1}); accm = same for -eps
        u64 accp[4][4], accm[4][4];
        #pragma unroll
        for (int kk = 0; kk < 4; ++kk)
            #pragma unroll
            for (int rr = 0; rr < 4; ++rr) { accp[kk][rr] = 0ull; accm[kk][rr] = 0ull; }

        #pragma unroll 1
        for (int h = 0; h < HID; ++h) {
            const ulonglong2* wq = (const ulonglong2*)(W2s + h * 512 + obase);
            ulonglong2 w01 = wq[0], w23 = wq[1];
            u64 wv[4] = {w01.x, w01.y, w23.x, w23.y};   // native (w2r, w2r+1)
            const ulonglong2* tq = (const ulonglong2*)(td + h * 18 + g * 8);
            ulonglong2 t0 = tq[0], t1 = tq[1], t2 = tq[2], t3 = tq[3];
            u64 tp[4] = {t0.x, t1.x, t2.x, t3.x};       // (t+, t+) per k
            u64 tm[4] = {t0.y, t1.y, t2.y, t3.y};       // (t-, t-) per k
            #pragma unroll
            for (int kk = 0; kk < 4; ++kk)
                #pragma unroll
                for (int rr = 0; rr < 4; ++rr) {
                    asm("fma.rn.f32x2 %0, %1, %2, %0;"
                        : "+l"(accp[kk][rr]) : "l"(tp[kk]), "l"(wv[rr]));
                    asm("fma.rn.f32x2 %0, %1, %2, %0;"
                        : "+l"(accm[kk][rr]) : "l"(tm[kk]), "l"(wv[rr]));
                }
        }
        {   // + b2: one rounded add per element; native (b2r, b2r+1) pairs
            const ulonglong2* bq = (const ulonglong2*)(b2s + obase);
            ulonglong2 b01 = bq[0], b23 = bq[1];
            u64 bv[4] = {b01.x, b01.y, b23.x, b23.y};
            #pragma unroll
            for (int rr = 0; rr < 4; ++rr)
                #pragma unroll
                for (int kk = 0; kk < 4; ++kk) {
                    asm("add.rn.f32x2 %0, %1, %2;"
                        : "=l"(accp[kk][rr]) : "l"(accp[kk][rr]), "l"(bv[rr]));
                    asm("add.rn.f32x2 %0, %1, %2;"
                        : "=l"(accm[kk][rr]) : "l"(accm[kk][rr]), "l"(bv[rr]));
                }
        }

        // ---- Phase 3: packed FD + symmetrized-weight contraction (reg-only) ----
        // u/v loaded here (broadcast LDS) to keep phase-2 live set minimal
        float uL[8], vL[8];
        #pragma unroll
        for (int r = 0; r < 8; ++r) {
            uL[r] = uvS[p * 16 + r];
            vL[r] = uvS[p * 16 + 8 + r];
        }
        const float wj = uL[ii] * HRECIP * uL[jj];   // u_i*u_j*0.5/2eps
        const float xj = uL[ii] * HRECIP * vL[jj];   // u_i*v_j*0.5/2eps

        #pragma unroll
        for (int kk = 0; kk < 4; ++kk) {
            const int k = g * 4 + kk;
            float dg[8];
            #pragma unroll
            for (int rr = 0; rr < 4; ++rr) {
                u64 d;
                asm("fma.rn.f32x2 %0, %1, %2, %3;"   // rn(c+ - c-), both lanes
                    : "=l"(d) : "l"(accm[kk][rr]), "l"(NEG1), "l"(accp[kk][rr]));
                asm("mov.b64 {%0,%1}, %2;"
                    : "=f"(dg[2*rr]), "=f"(dg[2*rr+1]) : "l"(d));
            }
            float S1 = 0.0f, S2 = 0.0f;
            #pragma unroll
            for (int r = 0; r < 8; ++r) {
                if (r != k) S1 = fmaf(vL[r], dg[r], S1);   // mask on l (= r)
                S2 = fmaf(uL[r], dg[r], S2);               // unmasked in r
            }
            const float vk = vL[k];
            partial = fmaf(vk * wj, S1, partial);
            if (jj != k)                                   // mask on j for S2 term
                partial = fmaf(vk * xj, S2, partial);
        }
    }

    // ---- reduce: 2 warps per point, finalize ----
    #pragma unroll
    for (int s = 16; s; s >>= 1) partial += __shfl_xor_sync(0xffffffffu, partial, s);
    if (lane == 0) redS[warp] = partial;
    __syncthreads();
    if (tid < PTS_PER_CTA) {
        const int p2 = tid;
        float R = redS[2 * p2] + redS[2 * p2 + 1];
        const int n = n0 + p2;
        const float* g = gS + (n & 7) * 64;
        const float* uL = uvS + p2 * 16;
        const float* vL = uvS + p2 * 16 + 8;
        float guu = 0.0f, gvv = 0.0f, guv = 0.0f;
        #pragma unroll
        for (int i = 0; i < D; ++i) {
            float gu = 0.0f, gv = 0.0f;
            #pragma unroll
            for (int j = 0; j < D; ++j) {
                float ge = g[i * 8 + j];
                gu = fmaf(ge, uL[j], gu);
                gv = fmaf(ge, vL[j], gv);
            }
            guu = fmaf(uL[i], gu, guu);
            gvv = fmaf(vL[i], gv, gvv);
            guv = fmaf(uL[i], gv, guv);
        }
        float den = fmaxf(guu * gvv - guv * guv, 1e-8f);
        out[n] = R / den;
    }
}

extern "C" void kernel_launch(void* const* d_in, const int* in_sizes, int n_in,
                              void* d_out, int out_size)
{
    const float* positions = (const float*)d_in[0];
    const float* u         = (const float*)d_in[1];
    const float* v         = (const float*)d_in[2];
    const float* chol      = (const float*)d_in[3];
    const float* W1        = (const float*)d_in[4];
    const float* b1        = (const float*)d_in[5];
    const float* W2        = (const float*)d_in[6];
    const float* b2        = (const float*)d_in[7];
    float* out = (float*)d_out;

    cudaFuncSetAttribute(rg_kernel, cudaFuncAttributeMaxDynamicSharedMemorySize,
                         SMEM_BYTES);
    rg_kernel<<<GRID, THREADS, SMEM_BYTES>>>(positions, u, v, chol,
                                             W1, b1, W2, b2, out);
}

// round 16
// speedup vs baseline: 1.3897x; 1.3897x over previous
#include <cuda_runtime.h>
#include <math.h>

#define D 8
#define HID 64
#define PTS_PER_CTA 8
#define THREADS 256
#define GRID 148
#define NBATCH 1024
#define EPSF 1e-4f
#define TWOEPSF 2e-4f

typedef unsigned long long u64;

__device__ __forceinline__ u64 pack2(float lo, float hi) {
    u64 r; asm("mov.b64 %0, {%1, %2};" : "=l"(r) : "f"(lo), "f"(hi)); return r;
}

// XLA EmitFastTanh (with_fma=true): verified bit-match with reference in R3.
__device__ __forceinline__ float xla_tanh(float x) {
    const float kClamp = 7.90531110763549805f;
    float xc = fminf(fmaxf(x, -kClamp), kClamp);
    float x2 = __fmul_rn(xc, xc);
    float num = -2.76076847742355e-16f;
    num = __fmaf_rn(x2, num,  2.00018790482477e-13f);
    num = __fmaf_rn(x2, num, -8.60467152213735e-11f);
    num = __fmaf_rn(x2, num,  5.12229709037114e-08f);
    num = __fmaf_rn(x2, num,  1.48572235717979e-05f);
    num = __fmaf_rn(x2, num,  6.37261928875436e-04f);
    num = __fmaf_rn(x2, num,  4.89352455891786e-03f);
    num = __fmul_rn(xc, num);
    float den = 1.19825839466702e-06f;
    den = __fmaf_rn(x2, den,  1.18534705686654e-04f);
    den = __fmaf_rn(x2, den,  2.26843463243900e-03f);
    den = __fmaf_rn(x2, den,  4.89352518554385e-03f);
    float r = __fdiv_rn(num, den);
    return (fabsf(x) < 0.0004f) ? x : r;
}

// smem float offsets
#define OFF_W2  0                        // 32768
#define OFF_W1  (OFF_W2 + 32768)         // 512
#define OFF_B1  (OFF_W1 + 512)           // 64
#define OFF_B2  (OFF_B1 + 64)            // 512
#define OFF_G   (OFF_B2 + 512)           // 512
#define OFF_UV  (OFF_G + 512)            // 128
#define OFF_T2  (OFF_UV + 128)           // 8 pts * 64h * 8k * 2 = 8192
#define OFF_RED (OFF_T2 + 8192)          // 16
#define SMEM_FLOATS (OFF_RED + 16)
#define SMEM_BYTES (SMEM_FLOATS * 4)

__global__ void __launch_bounds__(THREADS, 1)
rg_kernel(const float* __restrict__ pos, const float* __restrict__ uu_g,
          const float* __restrict__ vv_g, const float* __restrict__ chol,
          const float* __restrict__ W1,  const float* __restrict__ b1,
          const float* __restrict__ W2,  const float* __restrict__ b2,
          float* __restrict__ out)
{
    extern __shared__ float sm[];
    float* W2s = sm + OFF_W2;
    float* W1s = sm + OFF_W1;
    float* b1s = sm + OFF_B1;
    float* b2s = sm + OFF_B2;
    float* gS  = sm + OFF_G;
    float* uvS = sm + OFF_UV;
    float* t2s = sm + OFF_T2;
    float* redS= sm + OFF_RED;

    const int tid  = threadIdx.x;
    const int lane = tid & 31;
    const int warp = tid >> 5;

    // ---- persistent staging: W2 via cp.async (waited before first phase 2) ----
    {
        unsigned int w2dst =
            (unsigned int)__cvta_generic_to_shared(W2s) + (unsigned)tid * 16u;
        const char* w2src = (const char*)W2 + (size_t)tid * 16u;
        #pragma unroll
        for (int it = 0; it < 32; ++it)
            asm volatile("cp.async.cg.shared.global [%0], [%1], 16;"
                         :: "r"(w2dst + it * THREADS * 16),
                            "l"(w2src + (size_t)it * THREADS * 16) : "memory");
        asm volatile("cp.async.commit_group;" ::: "memory");
    }
    if (tid < 128) {
        ((float4*)W1s)[tid] = ((const float4*)W1)[tid];
        ((float4*)b2s)[tid] = ((const float4*)b2)[tid];
    }
    if (tid < 64) b1s[tid] = b1[tid];
    __syncthreads();   // W1/b1/b2 visible (W2 still in flight); bar A for batch 0

    const int pair = warp >> 1;
    const int slot = tid & 63;               // i = slot>>3, j = slot&7
    const int pA   = 2 * pair, pB = 2 * pair + 1;
    const int obase = slot * 8;
    const int jj   = slot & 7;
    const int ii   = slot >> 3;
    const float HRECIP = 0.5f / TWOEPSF;     // 0.5 * rn(1/2e-4); unamplified use

    for (int batch = blockIdx.x; batch < NBATCH; batch += gridDim.x) {
        const int n0 = batch * PTS_PER_CTA;

        // ---- per-batch inputs: uv + metric g (overlap first-batch W2 fetch) ----
        if (tid < PTS_PER_CTA * 16) {
            int pp = tid >> 4, q = tid & 15;
            uvS[tid] = (q < 8) ? uu_g[(n0 + pp) * 8 + q]
                               : vv_g[(n0 + pp) * 8 + (q - 8)];
        }
        for (int idx = tid; idx < 512; idx += THREADS) {
            int pp = idx >> 6, ij = idx & 63, i = ij >> 3, j = ij & 7;
            int mm = (i < j) ? i : j;
            float acc = (i == j) ? 1e-6f : 0.0f;
            for (int m = 0; m <= mm; ++m)
                acc = fmaf(chol[pp * 64 + i * 8 + m],
                           chol[pp * 64 + j * 8 + m], acc);
            gS[idx] = acc;
        }

        // ---- Phase 1: one warp per point; t = fast_tanh((pos +- eps e_k)@W1+b1) ----
        {
            const int p1 = warp;
            const int n  = n0 + p1;
            float posr[D];
            #pragma unroll
            for (int j = 0; j < D; ++j) posr[j] = pos[n * 8 + j];
            const int h0 = lane, h1 = lane + 32;
            const float bb0 = b1s[h0], bb1 = b1s[h1];
            #pragma unroll
            for (int m = 0; m < 16; ++m) {   // m = k*2 + s; s=0 -> +eps, 1 -> -eps
                int k = m >> 1;
                float sgn = (m & 1) ? -EPSF : EPSF;
                float acc0 = 0.0f, acc1 = 0.0f;
                #pragma unroll
                for (int j = 0; j < D; ++j) {
                    float pj = posr[j];
                    if (j == k) pj = __fadd_rn(pj, sgn);     // one rounding
                    acc0 = fmaf(pj, W1s[j * 64 + h0], acc0); // ascending-j chain
                    acc1 = fmaf(pj, W1s[j * 64 + h1], acc1);
                }
                float t0 = xla_tanh(__fadd_rn(acc0, bb0));
                float t1 = xla_tanh(__fadd_rn(acc1, bb1));
                t2s[((p1 * 64 + h0) * 8 + k) * 2 + (m & 1)] = t0;
                t2s[((p1 * 64 + h1) * 8 + k) * 2 + (m & 1)] = t1;
            }
        }
        asm volatile("cp.async.wait_group 0;" ::: "memory");  // no-op after batch 0
        __syncthreads();   // bar B: t2s/uv/g (and W2 on batch 0) visible

        // per-point u, v and combined weights
        float uA[8], vA[8], uB[8], vB[8];
        #pragma unroll
        for (int r = 0; r < 8; ++r) {
            uA[r] = uvS[pA * 16 + r];     vA[r] = uvS[pA * 16 + 8 + r];
            uB[r] = uvS[pB * 16 + r];     vB[r] = uvS[pB * 16 + 8 + r];
        }
        const float wjA = uA[ii] * HRECIP * uA[jj];
        const float xjA = uA[ii] * HRECIP * vA[jj];
        const float wjB = uB[ii] * HRECIP * uB[jj];
        const float xjB = uB[ii] * HRECIP * vB[jj];

        float partialA = 0.0f, partialB = 0.0f;

        #pragma unroll 1
        for (int g = 0; g < 2; ++g) {        // k-groups {0..3}, {4..7}
            // ---- Phase 2: ascending-h fma chains, packed +/-, 2 points ----
            u64 accA[4][8], accB[4][8];
            #pragma unroll
            for (int kk = 0; kk < 4; ++kk)
                #pragma unroll
                for (int r = 0; r < 8; ++r) { accA[kk][r] = 0ull; accB[kk][r] = 0ull; }

            #pragma unroll 2
            for (int h = 0; h < HID; ++h) {
                const float4* w2q = (const float4*)(W2s + h * 512 + obase);
                float4 wa = w2q[0], wb = w2q[1];
                u64 w2d[8];
                w2d[0] = pack2(wa.x, wa.x); w2d[1] = pack2(wa.y, wa.y);
                w2d[2] = pack2(wa.z, wa.z); w2d[3] = pack2(wa.w, wa.w);
                w2d[4] = pack2(wb.x, wb.x); w2d[5] = pack2(wb.y, wb.y);
                w2d[6] = pack2(wb.z, wb.z); w2d[7] = pack2(wb.w, wb.w);
                ulonglong2 tA0 = *(const ulonglong2*)(t2s + pA * 1024 + h * 16 + g * 8);
                ulonglong2 tA1 = *(const ulonglong2*)(t2s + pA * 1024 + h * 16 + g * 8 + 4);
                ulonglong2 tB0 = *(const ulonglong2*)(t2s + pB * 1024 + h * 16 + g * 8);
                ulonglong2 tB1 = *(const ulonglong2*)(t2s + pB * 1024 + h * 16 + g * 8 + 4);
                u64 tvA[4] = {tA0.x, tA0.y, tA1.x, tA1.y};
                u64 tvB[4] = {tB0.x, tB0.y, tB1.x, tB1.y};
                #pragma unroll
                for (int kk = 0; kk < 4; ++kk)
                    #pragma unroll
                    for (int r = 0; r < 8; ++r) {
                        asm("fma.rn.f32x2 %0, %1, %2, %0;"
                            : "+l"(accA[kk][r]) : "l"(tvA[kk]), "l"(w2d[r]));
                        asm("fma.rn.f32x2 %0, %1, %2, %0;"
                            : "+l"(accB[kk][r]) : "l"(tvB[kk]), "l"(w2d[r]));
                    }
            }
            {   // + b2: one rounded add per element (ref rounding)
                const float4* b2q = (const float4*)(b2s + obase);
                float4 ba = b2q[0], bb = b2q[1];
                float bv[8] = {ba.x, ba.y, ba.z, ba.w, bb.x, bb.y, bb.z, bb.w};
                #pragma unroll
                for (int r = 0; r < 8; ++r) {
                    u64 bb2 = pack2(bv[r], bv[r]);
                    #pragma unroll
                    for (int kk = 0; kk < 4; ++kk) {
                        asm("add.rn.f32x2 %0, %1, %2;"
                            : "=l"(accA[kk][r]) : "l"(accA[kk][r]), "l"(bb2));
                        asm("add.rn.f32x2 %0, %1, %2;"
                            : "=l"(accB[kk][r]) : "l"(accB[kk][r]), "l"(bb2));
                    }
                }
            }

            // ---- Phase 3: all-register FD + symmetrized-weight contraction ----
            #pragma unroll
            for (int kk = 0; kk < 4; ++kk) {
                const int k = g * 4 + kk;
                float dgA[8], dgB[8];
                #pragma unroll
                for (int r = 0; r < 8; ++r) {
                    float cp, cm;
                    asm("mov.b64 {%0,%1}, %2;" : "=f"(cp), "=f"(cm) : "l"(accA[kk][r]));
                    dgA[r] = __fsub_rn(cp, cm);          // exact (Sterbenz)
                    asm("mov.b64 {%0,%1}, %2;" : "=f"(cp), "=f"(cm) : "l"(accB[kk][r]));
                    dgB[r] = __fsub_rn(cp, cm);
                }
                float S1A = 0.0f, S2A = 0.0f, S1B = 0.0f, S2B = 0.0f;
                #pragma unroll
                for (int r = 0; r < 8; ++r) {
                    if (r != k) {                        // mask on l (= r)
                        S1A = fmaf(vA[r], dgA[r], S1A);
                        S1B = fmaf(vB[r], dgB[r], S1B);
                    }
                    S2A = fmaf(uA[r], dgA[r], S2A);      // unmasked in r
                    S2B = fmaf(uB[r], dgB[r], S2B);
                }
                const float vkA = vA[k], vkB = vB[k];
                partialA = fmaf(vkA * wjA, S1A, partialA);
                partialB = fmaf(vkB * wjB, S1B, partialB);
                if (jj != k) {                           // mask on j for S2 term
                    partialA = fmaf(vkA * xjA, S2A, partialA);
                    partialB = fmaf(vkB * xjB, S2B, partialB);
                }
            }
        }

        // ---- reduce 64 threads per point, finalize ----
        #pragma unroll
        for (int s = 16; s; s >>= 1) {
            partialA += __shfl_xor_sync(0xffffffffu, partialA, s);
            partialB += __shfl_xor_sync(0xffffffffu, partialB, s);
        }
        if (lane == 0) { redS[warp * 2] = partialA; redS[warp * 2 + 1] = partialB; }
        __syncthreads();   // bar C
        if (tid < PTS_PER_CTA) {
            const int p = tid;
            const int w0 = 2 * (p >> 1);
            float R = redS[w0 * 2 + (p & 1)] + redS[(w0 + 1) * 2 + (p & 1)];
            const int n = n0 + p;
            const float* g = gS + (n & 7) * 64;
            const float* uL = uvS + p * 16;
            const float* vL = uvS + p * 16 + 8;
            float guu = 0.0f, gvv = 0.0f, guv = 0.0f;
            #pragma unroll
            for (int i = 0; i < D; ++i) {
                float gu = 0.0f, gv = 0.0f;
                #pragma unroll
                for (int j = 0; j < D; ++j) {
                    float ge = g[i * 8 + j];
                    gu = fmaf(ge, uL[j], gu);
                    gv = fmaf(ge, vL[j], gv);
                }
                guu = fmaf(uL[i], gu, guu);
                gvv = fmaf(vL[i], gv, gvv);
                guv = fmaf(uL[i], gv, guv);
            }
            float den = fmaxf(guu * gvv - guv * guv, 1e-8f);
            out[n] = R / den;
        }
        __syncthreads();   // bar A: epilogue/phase-3 reads done before next writes
    }
}

extern "C" void kernel_launch(void* const* d_in, const int* in_sizes, int n_in,
                              void* d_out, int out_size)
{
    const float* positions = (const float*)d_in[0];
    const float* u         = (const float*)d_in[1];
    const float* v         = (const float*)d_in[2];
    const float* chol      = (const float*)d_in[3];
    const float* W1        = (const float*)d_in[4];
    const float* b1        = (const float*)d_in[5];
    const float* W2        = (const float*)d_in[6];
    const float* b2        = (const float*)d_in[7];
    float* out = (float*)d_out;

    cudaFuncSetAttribute(rg_kernel, cudaFuncAttributeMaxDynamicSharedMemorySize,
                         SMEM_BYTES);
    rg_kernel<<<GRID, THREADS, SMEM_BYTES>>>(positions, u, v, chol,
                                             W1, b1, W2, b2, out);
}